// round 6
// baseline (speedup 1.0000x reference)
#include <cuda_runtime.h>
#include <cstdint>

// SNN: fc1(21->100) -> 25-step Leaky -> fc2(100->10) -> Leaky
// T=1: one thread per sample. Bitwise-identical numerics to R5:
//  - cur1: acc=0, FMA k ascending, + b1 at end
//  - cur2: ordered sum of W2 columns over active j ascending (+0.0 zero-row
//    pads exact), + b2 pair-adds at end; add2 = per-lane scalar RN
//  - layer-1: mem = fma(beta,mem,cur); if(prev spike) mem = fsub(mem, 1.0)
//  - layer-2: mem = fsub(fma(beta,mem,cur), prev_spk)
// mem1[100] in regs; cur1 in SMEM float4[25][128] (conflict-free LDS.128);
// walk does all 5 output chains in one lane (3 LDS + 5 add2 per bit).

#define BETA    0.99f
#define NSTEPS  25
#define H1      100
#define H2      10
#define NIN     21
#define TPB     128

typedef unsigned long long u64;
typedef unsigned int u32;

__device__ __forceinline__ u64 add2(u64 a, u64 b) {
    u64 d;
    asm("add.rn.f32x2 %0, %1, %2;" : "=l"(d) : "l"(a), "l"(b));
    return d;
}
__device__ __forceinline__ void unpack2(u64 v, float& a, float& b) {
    asm("mov.b64 {%0, %1}, %2;" : "=f"(a), "=f"(b) : "l"(v));
}

// dynamic smem layout (floats):
//   cur1_s : [25][128] float4   @ 0        (12800 floats)
//   W2s    : [104][12]          @ 12800    (1248 floats; rows 100..103 zero)
//   b2s    : [12]               @ 14048
//   W1s    : [100][24]          @ 14064
//   b1s    : [100]              @ 16464
#define OFF_CUR1 0
#define OFF_W2   12800
#define OFF_B2   14048
#define OFF_W1   14064
#define OFF_B1   16464
#define SMEM_FLOATS 16564
#define SMEM_BYTES (SMEM_FLOATS * 4)

__global__ __launch_bounds__(TPB, 3)
void snn_kernel(const float* __restrict__ x,
                const float* __restrict__ W1,
                const float* __restrict__ b1,
                const float* __restrict__ W2,
                const float* __restrict__ b2,
                float* __restrict__ out,
                int B)
{
    extern __shared__ __align__(16) float smem[];
    float* cur1_s = smem + OFF_CUR1;
    float* W2s    = smem + OFF_W2;
    float* b2s    = smem + OFF_B2;
    float* W1s    = smem + OFF_W1;
    float* b1s    = smem + OFF_B1;

    const int tid = threadIdx.x;

    for (int idx = tid; idx < H1 * NIN; idx += TPB)
        W1s[(idx / NIN) * 24 + (idx % NIN)] = W1[idx];
    for (int idx = tid; idx < H2 * H1; idx += TPB)
        W2s[(idx % H1) * 12 + (idx / H1)] = W2[idx];     // W2 is [10][100]
    if (tid < 48) W2s[100 * 12 + tid] = 0.0f;            // zero rows 100..103
    if (tid < H1) b1s[tid] = b1[tid];
    if (tid < 12) b2s[tid] = (tid < H2) ? b2[tid] : 0.0f;
    __syncthreads();

    const int sample = blockIdx.x * TPB + tid;
    if (sample >= B) return;

    // ---- x row ----
    float xr[NIN];
    const float* xrow = x + (size_t)sample * NIN;
#pragma unroll
    for (int i = 0; i < NIN; i++) xr[i] = __ldg(xrow + i);

    // ---- cur1 (all 100): acc=0, FMA k ascending, + b1; store to smem ----
#pragma unroll 1
    for (int g = 0; g < 25; g++) {
        float4 cv;
        float* cp = &cv.x;
#pragma unroll
        for (int i = 0; i < 4; i++) {
            const int j = g * 4 + i;
            const float* w = &W1s[j * 24];
            float acc = 0.0f;
#pragma unroll
            for (int k = 0; k < NIN; k++)
                acc = __fmaf_rn(xr[k], w[k], acc);
            cp[i] = __fadd_rn(acc, b1s[j]);
        }
        *(float4*)&cur1_s[(g * TPB + tid) * 4] = cv;
    }

    // ---- state ----
    float mem1[H1];
#pragma unroll
    for (int j = 0; j < H1; j++) mem1[j] = 0.0f;
    u32 M0 = 0, M1 = 0, M2 = 0, M3 = 0;     // 25 bits each, j = seg*25 + bit

    float mem2[H2], spk2[H2];
#pragma unroll
    for (int k = 0; k < H2; k++) { mem2[k] = 0.0f; spk2[k] = 0.0f; }

    const u64 B0 = *(const u64*)&b2s[0];
    const u64 B1 = *(const u64*)&b2s[2];
    const u64 B2 = *(const u64*)&b2s[4];
    const u64 B3 = *(const u64*)&b2s[6];
    const u64 B4 = *(const u64*)&b2s[8];

    float* spkout = out + (size_t)sample * H2;
    float* memout = spkout + (size_t)NSTEPS * B * H2;
    const size_t step_stride = (size_t)B * H2;

#pragma unroll 1
    for (int t = 0; t < NSTEPS; t++) {
        // ---- layer-1: mem = fma(beta,mem,cur); if(prev spike) mem -= 1.0 ----
        u32 N0 = 0, N1 = 0, N2 = 0, N3 = 0;
#pragma unroll
        for (int g = 0; g < 25; g++) {
            float4 cv = *(const float4*)&cur1_s[(g * TPB + tid) * 4];
            const float* cp = &cv.x;
#pragma unroll
            for (int i = 0; i < 4; i++) {
                const int j = g * 4 + i;
                const int seg = j / 25, bit = j % 25;
                const u32 om = (seg == 0) ? M0 : (seg == 1) ? M1 : (seg == 2) ? M2 : M3;
                float mv = __fmaf_rn(BETA, mem1[j], cp[i]);
                if ((om >> bit) & 1u) mv = __fsub_rn(mv, 1.0f);
                mem1[j] = mv;
                if (mv > 1.0f) {
                    if (seg == 0) N0 |= (1u << bit);
                    else if (seg == 1) N1 |= (1u << bit);
                    else if (seg == 2) N2 |= (1u << bit);
                    else N3 |= (1u << bit);
                }
            }
        }
        M0 = N0; M1 = N1; M2 = N2; M3 = N3;

        // ---- cur2: ordered column-sum over active j; 5 chains; unroll-2 ----
        u64 a0 = 0ull, a1 = 0ull, a2 = 0ull, a3 = 0ull, a4 = 0ull;

#define WALK(MM, RB)                                                          \
        {                                                                     \
            u32 m = (MM);                                                     \
            while (m) {                                                       \
                int p0 = __ffs(m) - 1; m &= m - 1;                            \
                int p1 = __ffs(m) - 1;                                        \
                p1 = (m == 0) ? (100 - (RB)) : p1;                            \
                m &= m - 1;                                                   \
                const float* w0 = &W2s[((RB) + p0) * 12];                     \
                const float* w1 = &W2s[((RB) + p1) * 12];                     \
                ulonglong2 qa0 = *(const ulonglong2*)(w0);                    \
                ulonglong2 qb0 = *(const ulonglong2*)(w0 + 4);                \
                u64        qc0 = *(const u64*)(w0 + 8);                       \
                ulonglong2 qa1 = *(const ulonglong2*)(w1);                    \
                ulonglong2 qb1 = *(const ulonglong2*)(w1 + 4);                \
                u64        qc1 = *(const u64*)(w1 + 8);                       \
                a0 = add2(a0, qa0.x); a1 = add2(a1, qa0.y);                   \
                a2 = add2(a2, qb0.x); a3 = add2(a3, qb0.y);                   \
                a4 = add2(a4, qc0);                                           \
                a0 = add2(a0, qa1.x); a1 = add2(a1, qa1.y);                   \
                a2 = add2(a2, qb1.x); a3 = add2(a3, qb1.y);                   \
                a4 = add2(a4, qc1);                                           \
            }                                                                 \
        }
        WALK(M0, 0)
        WALK(M1, 25)
        WALK(M2, 50)
        WALK(M3, 75)
#undef WALK

        a0 = add2(a0, B0);
        a1 = add2(a1, B1);
        a2 = add2(a2, B2);
        a3 = add2(a3, B3);
        a4 = add2(a4, B4);

        float c[H2];
        unpack2(a0, c[0], c[1]);
        unpack2(a1, c[2], c[3]);
        unpack2(a2, c[4], c[5]);
        unpack2(a3, c[6], c[7]);
        unpack2(a4, c[8], c[9]);

        // ---- layer-2: mem = fl(fma(beta,mem,cur) - prev_spk) ----
#pragma unroll
        for (int k = 0; k < H2; k++) {
            float mv = __fsub_rn(__fmaf_rn(BETA, mem2[k], c[k]), spk2[k]);
            mem2[k] = mv;
            spk2[k] = (mv > 1.0f) ? 1.0f : 0.0f;
        }

        // ---- stores (float2, 8B aligned) ----
#pragma unroll
        for (int k = 0; k < 5; k++) {
            float2 sv; sv.x = spk2[2 * k]; sv.y = spk2[2 * k + 1];
            *(float2*)(spkout + 2 * k) = sv;
            float2 mv; mv.x = mem2[2 * k]; mv.y = mem2[2 * k + 1];
            *(float2*)(memout + 2 * k) = mv;
        }

        spkout += step_stride;
        memout += step_stride;
    }
}

extern "C" void kernel_launch(void* const* d_in, const int* in_sizes, int n_in,
                              void* d_out, int out_size) {
    const float* x  = (const float*)d_in[0];
    const float* W1 = (const float*)d_in[1];
    const float* b1 = (const float*)d_in[2];
    const float* W2 = (const float*)d_in[3];
    const float* b2 = (const float*)d_in[4];
    float* out = (float*)d_out;
    const int B = in_sizes[0] / NIN;

    static bool attr_set = false;  // idempotent attribute, not a work guard
    if (!attr_set) {
        cudaFuncSetAttribute(snn_kernel,
                             cudaFuncAttributeMaxDynamicSharedMemorySize,
                             SMEM_BYTES);
        attr_set = true;
    }

    const int grid = (B + TPB - 1) / TPB;
    snn_kernel<<<grid, TPB, SMEM_BYTES>>>(x, W1, b1, W2, b2, out, B);
}